// round 16
// baseline (speedup 1.0000x reference)
#include <cuda_runtime.h>
#include <cstdint>

// Problem constants: B=16384, F=16, V=300000, D=10
#define BSZ   16384
#define FDIM  16
#define VDIM  300000
#define DDIM  10
#define DPAD  12                  // padded E row stride (48B, 16B-aligned rows)
#define NPAIR 120                 // F*(F-1)/2
#define OUTW  1376                // 120*10 + 16*10 + 16
#define OUTW4 (OUTW / 4)          // 344
#define SPB   2                   // samples per block (512 threads, 256 per sample)
#define NTHR  (256 * SPB)

// Precomputed triu(k=1) pair table (i-major), packed i<<4 | j.
__constant__ unsigned char c_pair[NPAIR] = {
    0x01,0x02,0x03,0x04,0x05,0x06,0x07,0x08,0x09,0x0A,0x0B,0x0C,0x0D,0x0E,0x0F,
    0x12,0x13,0x14,0x15,0x16,0x17,0x18,0x19,0x1A,0x1B,0x1C,0x1D,0x1E,0x1F,
    0x23,0x24,0x25,0x26,0x27,0x28,0x29,0x2A,0x2B,0x2C,0x2D,0x2E,0x2F,
    0x34,0x35,0x36,0x37,0x38,0x39,0x3A,0x3B,0x3C,0x3D,0x3E,0x3F,
    0x45,0x46,0x47,0x48,0x49,0x4A,0x4B,0x4C,0x4D,0x4E,0x4F,
    0x56,0x57,0x58,0x59,0x5A,0x5B,0x5C,0x5D,0x5E,0x5F,
    0x67,0x68,0x69,0x6A,0x6B,0x6C,0x6D,0x6E,0x6F,
    0x78,0x79,0x7A,0x7B,0x7C,0x7D,0x7E,0x7F,
    0x89,0x8A,0x8B,0x8C,0x8D,0x8E,0x8F,
    0x9A,0x9B,0x9C,0x9D,0x9E,0x9F,
    0xAB,0xAC,0xAD,0xAE,0xAF,
    0xBC,0xBD,0xBE,0xBF,
    0xCD,0xCE,0xCF,
    0xDE,0xDF,
    0xEF
};

// L2 retention policy (R9 best): protect ALL emb lines (fraction 1.0).
__device__ __forceinline__ uint64_t mk_evict_last_policy() {
    uint64_t p;
    asm("createpolicy.fractional.L2::evict_last.b64 %0, 1.0;" : "=l"(p));
    return p;
}
__device__ __forceinline__ float4 ldg_el_f4(const float* p, uint64_t pol) {
    float4 r;
    asm("ld.global.nc.L2::cache_hint.v4.f32 {%0,%1,%2,%3}, [%4], %5;"
        : "=f"(r.x), "=f"(r.y), "=f"(r.z), "=f"(r.w) : "l"(p), "l"(pol));
    return r;
}
__device__ __forceinline__ float2 ldg_el_f2(const float* p, uint64_t pol) {
    float2 r;
    asm("ld.global.nc.L2::cache_hint.v2.f32 {%0,%1}, [%2], %3;"
        : "=f"(r.x), "=f"(r.y) : "l"(p), "l"(pol));
    return r;
}

__global__ __launch_bounds__(NTHR)
void feature_interact_kernel(const int*   __restrict__ x,    // [B, F]
                             const float* __restrict__ emb,  // [F, V, D]
                             const float* __restrict__ lin,  // [V, 1]
                             float*       __restrict__ out)  // [B, OUTW]
{
    __shared__ float E[SPB][FDIM * FDIM * DPAD]; // per-sample, rows padded 48B
    __shared__ float lin_s[SPB][FDIM];
    __shared__ unsigned char pij_s[NPAIR];       // packed i<<4|j

    const int tid = threadIdx.x;
    const int s   = tid >> 8;                    // sample slot 0/1
    const int t   = tid & 255;                   // thread within sample
    const int b   = blockIdx.x * SPB + s;

    // lin gather, once per sample (hidden under the big gathers).
    if (t < FDIM) {
        lin_s[s][t] = __ldg(&lin[__ldg(&x[b * FDIM + t])]);
    }
    // pair table: straight copy from constant memory.
    if (tid < NPAIR) {
        pij_s[tid] = c_pair[tid];
    }

    // Gather phase: per sample, thread t owns (f = t>>4, g = t&15).
    // Identical per-thread shape to R15 (1 vector, 3 loads, evict_last(1.0)).
    {
        const int f = t >> 4;
        const int g = t & (FDIM - 1);
        const int idx = __ldg(&x[b * FDIM + f]);
        const float* base = emb + ((size_t)g * VDIM + (size_t)idx) * DDIM;
        const uint64_t pol = mk_evict_last_policy();

        float* dst = E[s] + t * DPAD;            // t*48B: 16B-aligned
        if ((((uintptr_t)base) & 15) == 0) {
            // 16B-aligned src: f4 @0, f4 @16, f2 @32
            float4 a = ldg_el_f4(base, pol);
            float4 c = ldg_el_f4(base + 4, pol);
            float2 e = ldg_el_f2(base + 8, pol);
            *reinterpret_cast<float4*>(dst)     = a;
            *reinterpret_cast<float4*>(dst + 4) = c;
            *reinterpret_cast<float2*>(dst + 8) = e;
        } else {
            // 8B-aligned src: f2 @0, f4 @8, f4 @24
            float2 a = ldg_el_f2(base, pol);
            float4 c = ldg_el_f4(base + 2, pol);
            float4 e = ldg_el_f4(base + 6, pol);
            *reinterpret_cast<float2*>(dst)     = a;
            *reinterpret_cast<float2*>(dst + 2) = make_float2(c.x, c.y);
            *reinterpret_cast<float4*>(dst + 4) = make_float4(c.z, c.w, e.x, e.y);
            *reinterpret_cast<float2*>(dst + 8) = make_float2(e.z, e.w);
        }
    }
    __syncthreads();

    // Output phase: per sample, 344 float4 streaming stores (.cs — verified best).
    float4* orow4 = reinterpret_cast<float4*>(out + (size_t)b * OUTW);
    const float* Es = E[s];
    for (int q = t; q < OUTW4; q += 256) {
        float r[4];
        #pragma unroll
        for (int e = 0; e < 4; ++e) {
            const int k = q * 4 + e;
            float vv;
            if (k < NPAIR * DDIM) {
                int p = k / DDIM, d = k - p * DDIM;
                int ij = pij_s[p];
                int i = ij >> 4, j = ij & 15;
                vv = Es[(i * FDIM + j) * DPAD + d] * Es[(j * FDIM + i) * DPAD + d];
            } else if (k < NPAIR * DDIM + FDIM * DDIM) {
                int k2 = k - NPAIR * DDIM;
                int f = k2 / DDIM, d = k2 - f * DDIM;
                vv = Es[(f * FDIM + f) * DPAD + d];
            } else {
                vv = lin_s[s][k - (NPAIR * DDIM + FDIM * DDIM)];
            }
            r[e] = vv;
        }
        __stcs(&orow4[q], make_float4(r[0], r[1], r[2], r[3]));
    }
}

extern "C" void kernel_launch(void* const* d_in, const int* in_sizes, int n_in,
                              void* d_out, int out_size)
{
    const int*   x   = nullptr;
    const float* emb = nullptr;
    const float* lin = nullptr;
    for (int i = 0; i < n_in; ++i) {
        if      (in_sizes[i] == BSZ * FDIM)          x   = (const int*)d_in[i];
        else if (in_sizes[i] == FDIM * VDIM * DDIM)  emb = (const float*)d_in[i];
        else if (in_sizes[i] == VDIM)                lin = (const float*)d_in[i];
    }
    feature_interact_kernel<<<BSZ / SPB, NTHR>>>(x, emb, lin, (float*)d_out);
}

// round 17
// speedup vs baseline: 1.0095x; 1.0095x over previous
#include <cuda_runtime.h>
#include <cstdint>

// Problem constants: B=16384, F=16, V=300000, D=10
#define BSZ   16384
#define FDIM  16
#define VDIM  300000
#define DDIM  10
#define DPAD  12                  // padded E row stride (48B, 16B-aligned rows)
#define NPAIR 120                 // F*(F-1)/2
#define OUTW  1376                // 120*10 + 16*10 + 16
#define OUTW4 (OUTW / 4)          // 344

// Precomputed triu(k=1) pair table (i-major), packed i<<4 | j.
__constant__ unsigned char c_pair[NPAIR] = {
    0x01,0x02,0x03,0x04,0x05,0x06,0x07,0x08,0x09,0x0A,0x0B,0x0C,0x0D,0x0E,0x0F,
    0x12,0x13,0x14,0x15,0x16,0x17,0x18,0x19,0x1A,0x1B,0x1C,0x1D,0x1E,0x1F,
    0x23,0x24,0x25,0x26,0x27,0x28,0x29,0x2A,0x2B,0x2C,0x2D,0x2E,0x2F,
    0x34,0x35,0x36,0x37,0x38,0x39,0x3A,0x3B,0x3C,0x3D,0x3E,0x3F,
    0x45,0x46,0x47,0x48,0x49,0x4A,0x4B,0x4C,0x4D,0x4E,0x4F,
    0x56,0x57,0x58,0x59,0x5A,0x5B,0x5C,0x5D,0x5E,0x5F,
    0x67,0x68,0x69,0x6A,0x6B,0x6C,0x6D,0x6E,0x6F,
    0x78,0x79,0x7A,0x7B,0x7C,0x7D,0x7E,0x7F,
    0x89,0x8A,0x8B,0x8C,0x8D,0x8E,0x8F,
    0x9A,0x9B,0x9C,0x9D,0x9E,0x9F,
    0xAB,0xAC,0xAD,0xAE,0xAF,
    0xBC,0xBD,0xBE,0xBF,
    0xCD,0xCE,0xCF,
    0xDE,0xDF,
    0xEF
};

// L2 retention policy (R9 best): protect ALL emb lines (fraction 1.0).
__device__ __forceinline__ uint64_t mk_evict_last_policy() {
    uint64_t p;
    asm("createpolicy.fractional.L2::evict_last.b64 %0, 1.0;" : "=l"(p));
    return p;
}
__device__ __forceinline__ float4 ldg_el_f4(const float* p, uint64_t pol) {
    float4 r;
    asm("ld.global.nc.L2::cache_hint.v4.f32 {%0,%1,%2,%3}, [%4], %5;"
        : "=f"(r.x), "=f"(r.y), "=f"(r.z), "=f"(r.w) : "l"(p), "l"(pol));
    return r;
}
__device__ __forceinline__ float2 ldg_el_f2(const float* p, uint64_t pol) {
    float2 r;
    asm("ld.global.nc.L2::cache_hint.v2.f32 {%0,%1}, [%2], %3;"
        : "=f"(r.x), "=f"(r.y) : "l"(p), "l"(pol));
    return r;
}

__global__ __launch_bounds__(256)
void feature_interact_kernel(const int*   __restrict__ x,    // [B, F]
                             const float* __restrict__ emb,  // [F, V, D]
                             const float* __restrict__ lin,  // [V, 1]
                             float*       __restrict__ out)  // [B, OUTW]
{
    __shared__ float E[FDIM * FDIM * DPAD];      // E[f][g][d], rows padded to 48B
    __shared__ float lin_s[FDIM];
    __shared__ unsigned char pij_s[NPAIR];       // packed i<<4|j

    const int b = blockIdx.x;
    const int t = threadIdx.x;

    // lin gather, once per block (hidden under the big gathers).
    if (t < FDIM) {
        lin_s[t] = __ldg(&lin[__ldg(&x[b * FDIM + t])]);
    }
    // pair table: straight copy from constant memory.
    if (t < NPAIR) {
        pij_s[t] = c_pair[t];
    }

    // Gather phase: thread t owns (f = t>>4, g = t&15). 40B vector in 3 loads.
    // L1-cached (R6), L2 evict_last(1.0) (R9), padded 48B smem rows (R13).
    {
        const int f = t >> 4;
        const int g = t & (FDIM - 1);
        const int idx = __ldg(&x[b * FDIM + f]);
        const float* base = emb + ((size_t)g * VDIM + (size_t)idx) * DDIM;
        const uint64_t pol = mk_evict_last_policy();

        float* dst = E + t * DPAD;               // t*48B: 16B-aligned
        if ((((uintptr_t)base) & 15) == 0) {
            // 16B-aligned src: f4 @0, f4 @16, f2 @32
            float4 a = ldg_el_f4(base, pol);
            float4 c = ldg_el_f4(base + 4, pol);
            float2 e = ldg_el_f2(base + 8, pol);
            *reinterpret_cast<float4*>(dst)     = a;
            *reinterpret_cast<float4*>(dst + 4) = c;
            *reinterpret_cast<float2*>(dst + 8) = e;
        } else {
            // 8B-aligned src: f2 @0, f4 @8, f4 @24
            float2 a = ldg_el_f2(base, pol);
            float4 c = ldg_el_f4(base + 2, pol);
            float4 e = ldg_el_f4(base + 6, pol);
            *reinterpret_cast<float2*>(dst)     = a;                               // +0
            *reinterpret_cast<float2*>(dst + 2) = make_float2(c.x, c.y);           // +8
            *reinterpret_cast<float4*>(dst + 4) = make_float4(c.z, c.w, e.x, e.y); // +16
            *reinterpret_cast<float2*>(dst + 8) = make_float2(e.z, e.w);           // +32
        }
    }
    __syncthreads();

    // Output phase: 344 float4 streaming stores per row (.cs — verified best).
    float4* orow4 = reinterpret_cast<float4*>(out + (size_t)b * OUTW);
    for (int q = t; q < OUTW4; q += 256) {
        float r[4];
        #pragma unroll
        for (int e = 0; e < 4; ++e) {
            const int k = q * 4 + e;
            float vv;
            if (k < NPAIR * DDIM) {
                int p = k / DDIM, d = k - p * DDIM;
                int ij = pij_s[p];
                int i = ij >> 4, j = ij & 15;
                vv = E[(i * FDIM + j) * DPAD + d] * E[(j * FDIM + i) * DPAD + d];
            } else if (k < NPAIR * DDIM + FDIM * DDIM) {
                int k2 = k - NPAIR * DDIM;
                int f = k2 / DDIM, d = k2 - f * DDIM;
                vv = E[(f * FDIM + f) * DPAD + d];
            } else {
                vv = lin_s[k - (NPAIR * DDIM + FDIM * DDIM)];
            }
            r[e] = vv;
        }
        __stcs(&orow4[q], make_float4(r[0], r[1], r[2], r[3]));
    }
}

extern "C" void kernel_launch(void* const* d_in, const int* in_sizes, int n_in,
                              void* d_out, int out_size)
{
    const int*   x   = nullptr;
    const float* emb = nullptr;
    const float* lin = nullptr;
    for (int i = 0; i < n_in; ++i) {
        if      (in_sizes[i] == BSZ * FDIM)          x   = (const int*)d_in[i];
        else if (in_sizes[i] == FDIM * VDIM * DDIM)  emb = (const float*)d_in[i];
        else if (in_sizes[i] == VDIM)                lin = (const float*)d_in[i];
    }
    // Pin smem carveout to 50% (~114KB): still fits 8 CTAs x 12.3KB, and
    // guarantees >=114KB L1D for the gather stream (L1 hits proven valuable in R6).
    // Attribute set is not a stream operation — graph-capture safe; idempotent.
    cudaFuncSetAttribute(feature_interact_kernel,
                         cudaFuncAttributePreferredSharedMemoryCarveout, 50);
    feature_interact_kernel<<<BSZ, 256>>>(x, emb, lin, (float*)d_out);
}